// round 1
// baseline (speedup 1.0000x reference)
#include <cuda_runtime.h>
#include <math_constants.h>
#include <cstdint>

#define NN 10000
#define EE 160000
#define FDIM 16
#define LDIM 25
#define RPROJ (NN*LDIM)   // 250000 rows
#define FULLMASK 0xffffffffu

// ---------------- scratch (device globals: allocation-free) ----------------
__device__ int   g_count[NN];
__device__ int   g_row[NN+1];
__device__ int   g_head[NN];
__device__ int   g_col[EE];
__device__ int   g_esrc[EE];
__device__ float g_rbf[EE*16];
__device__ float g_sh[EE*25];
__device__ float g_escal[2][3][EE*4];   // [step][{b,g,g2}][p*4+h]
__device__ float g_q[RPROJ*16];
__device__ float g_k[RPROJ*16];
__device__ float g_v[RPROJ*16];

// ---------------- CSR build ----------------
__global__ void k_zero() {
    int i = blockIdx.x*blockDim.x + threadIdx.x;
    if (i < NN) g_count[i] = 0;
}

__global__ void k_hist(const int* __restrict__ ni) {
    int e = blockIdx.x*blockDim.x + threadIdx.x;
    if (e < EE) atomicAdd(&g_count[ni[2*e]], 1);
}

__global__ void k_scan() {   // one block of 1024 threads, 10 items each
    __shared__ int sums[1024];
    int t = threadIdx.x;
    int base = t*10;
    int loc[10];
    int run = 0;
    #pragma unroll
    for (int i = 0; i < 10; i++) {
        int idx = base + i;
        int c = (idx < NN) ? g_count[idx] : 0;
        loc[i] = run; run += c;
    }
    sums[t] = run;
    __syncthreads();
    for (int off = 1; off < 1024; off <<= 1) {
        int v = 0;
        if (t >= off) v = sums[t-off];
        __syncthreads();
        sums[t] += v;
        __syncthreads();
    }
    int excl = (t == 0) ? 0 : sums[t-1];
    #pragma unroll
    for (int i = 0; i < 10; i++) {
        int idx = base + i;
        if (idx < NN) { int r = excl + loc[i]; g_row[idx] = r; g_head[idx] = r; }
    }
    if (t == 1023) g_row[NN] = sums[1023];
}

__global__ void k_scatter(const int* __restrict__ ni) {
    int e = blockIdx.x*blockDim.x + threadIdx.x;
    if (e < EE) {
        int i = ni[2*e];
        int pos = atomicAdd(&g_head[i], 1);
        g_col[pos]  = ni[2*e+1];
        g_esrc[pos] = e;
    }
}

// ---------------- per-edge geometry: rbf + spherical harmonics ----------------
__global__ void k_geom(const float* __restrict__ disp) {
    int p = blockIdx.x*blockDim.x + threadIdx.x;
    if (p >= EE) return;
    int e = g_esrc[p];
    float dx = disp[3*e], dy = disp[3*e+1], dz = disp[3*e+2];
    float d  = sqrtf(dx*dx + dy*dy + dz*dz);
    float ds = fmaxf(d, 1e-9f);
    float inv = 1.0f/ds;
    float x = dx*inv, y = dy*inv, z = dz*inv;

    float env = 0.5f*(cospif(fminf(ds, 5.0f)*0.2f) + 1.0f);
    #pragma unroll
    for (int kk = 0; kk < 16; kk++) {
        float xx = (float)(kk+1)*ds*0.2f;
        float s  = (xx < 1e-6f) ? 1.0f : (sinpif(xx)/(CUDART_PI_F*xx));
        g_rbf[p*16+kk] = s*env;
    }

    float x2 = x*x, y2 = y*y, z2 = z*z;
    float sh[25];
    sh[0]  = 0.28209479177387814f;
    sh[1]  = 0.4886025119029199f*y;
    sh[2]  = 0.4886025119029199f*z;
    sh[3]  = 0.4886025119029199f*x;
    sh[4]  = 1.0925484305920792f*x*y;
    sh[5]  = 1.0925484305920792f*y*z;
    sh[6]  = 0.31539156525252005f*(3.0f*z2 - 1.0f);
    sh[7]  = 1.0925484305920792f*x*z;
    sh[8]  = 0.5462742152960396f*(x2 - y2);
    sh[9]  = 0.5900435899266435f*y*(3.0f*x2 - y2);
    sh[10] = 2.890611442640554f*x*y*z;
    sh[11] = 0.4570457994644658f*y*(5.0f*z2 - 1.0f);
    sh[12] = 0.3731763325901154f*z*(5.0f*z2 - 3.0f);
    sh[13] = 0.4570457994644658f*x*(5.0f*z2 - 1.0f);
    sh[14] = 1.445305721320277f*z*(x2 - y2);
    sh[15] = 0.5900435899266435f*x*(x2 - 3.0f*y2);
    sh[16] = 2.5033429417967046f*x*y*(x2 - y2);
    sh[17] = 1.7701307697799304f*y*z*(3.0f*x2 - y2);
    sh[18] = 0.9461746957575601f*x*y*(7.0f*z2 - 1.0f);
    sh[19] = 0.6690465435572892f*y*z*(7.0f*z2 - 3.0f);
    sh[20] = 0.10578554691520431f*(35.0f*z2*z2 - 30.0f*z2 + 3.0f);
    sh[21] = 0.6690465435572892f*x*z*(7.0f*z2 - 3.0f);
    sh[22] = 0.47308734787878004f*(x2 - y2)*(7.0f*z2 - 1.0f);
    sh[23] = 1.7701307697799304f*x*z*(x2 - 3.0f*y2);
    sh[24] = 0.6258357354491761f*(x2*x2 - 6.0f*x2*y2 + y2*y2);
    #pragma unroll
    for (int i = 0; i < 25; i++) g_sh[p*25+i] = sh[i];
}

// ---------------- edge scalars: b0 @ {Wb,Wg,Wg2}[s] for both steps ----------------
// Lane c<24 owns one (step, type, head) output column; weights live in registers.
__global__ void k_edgescal(const float* __restrict__ Wb,
                           const float* __restrict__ Wg,
                           const float* __restrict__ Wg2) {
    int lane = threadIdx.x & 31;
    int warp = (blockIdx.x*blockDim.x + threadIdx.x) >> 5;
    int nwarps = (gridDim.x*blockDim.x) >> 5;
    int c = lane;
    int t = c >> 3, s = (c >> 2) & 1, h = c & 3;
    float wreg[16];
    if (c < 24) {
        const float* W = (t == 0) ? Wb : ((t == 1) ? Wg : Wg2);
        #pragma unroll
        for (int f = 0; f < 16; f++) wreg[f] = __ldg(&W[s*64 + f*4 + h]);
    } else {
        #pragma unroll
        for (int f = 0; f < 16; f++) wreg[f] = 0.0f;
    }
    for (int p = warp; p < EE; p += nwarps) {
        float rv = (lane < 16) ? g_rbf[p*16+lane] : 0.0f;
        float out = 0.0f;
        #pragma unroll
        for (int f = 0; f < 16; f++)
            out = fmaf(__shfl_sync(FULLMASK, rv, f), wreg[f], out);
        if (c < 24) g_escal[s][t][p*4+h] = out;
    }
}

// ---------------- y init: y[:,0,:] = segsum(rbf*emb[Zj]) @ W_rb, rest 0 ----------------
__global__ void k_init(const float* __restrict__ emb, const float* __restrict__ Wrb,
                       const int* __restrict__ Z, float* __restrict__ y) {
    int tid = threadIdx.x;
    int w = tid >> 5, lane = tid & 31;
    int node = blockIdx.x*4 + w;
    if (node >= NN) return;
    int f = lane & 15, which = lane >> 4;
    int rs = g_row[node], ren = g_row[node+1];
    float acc = 0.0f;
    for (int p = rs + which; p < ren; p += 2) {
        int j = g_col[p];
        int z = Z[j];
        acc = fmaf(g_rbf[p*16+f], __ldg(&emb[z*16+f]), acc);
    }
    acc += __shfl_xor_sync(FULLMASK, acc, 16);
    float out = 0.0f;
    #pragma unroll
    for (int ff = 0; ff < 16; ff++)
        out = fmaf(__shfl_sync(FULLMASK, acc, ff), __ldg(&Wrb[ff*16+f]), out);
    float* yp = y + (size_t)node*400;
    if (lane < 16) yp[f] = out;
    for (int i = 16 + lane; i < 400; i += 32) yp[i] = 0.0f;
}

// ---------------- q,k,v projection: (N*L,16) x (16,16) x3 ----------------
__global__ void k_proj(const float* __restrict__ y,
                       const float* __restrict__ Wq,
                       const float* __restrict__ Wk,
                       const float* __restrict__ Wv) {
    __shared__ float yt[16][17];
    __shared__ float wq[16][16], wk[16][16], wv[16][16];
    int tx = threadIdx.x, ty = threadIdx.y;
    int tid = ty*16 + tx;
    wq[ty][tx] = Wq[tid]; wk[ty][tx] = Wk[tid]; wv[ty][tx] = Wv[tid];
    int r = blockIdx.x*16 + ty;
    yt[ty][tx] = (r < RPROJ) ? y[(size_t)r*16 + tx] : 0.0f;
    __syncthreads();
    if (r >= RPROJ) return;
    float aq = 0.0f, ak = 0.0f, av = 0.0f;
    #pragma unroll
    for (int f = 0; f < 16; f++) {
        float yv = yt[ty][f];
        aq = fmaf(yv, wq[f][tx], aq);
        ak = fmaf(yv, wk[f][tx], ak);
        av = fmaf(yv, wv[f][tx], av);
    }
    g_q[(size_t)r*16+tx] = aq;
    g_k[(size_t)r*16+tx] = ak;
    g_v[(size_t)r*16+tx] = av;
}

// ---------------- attention + aggregate + Wo, one warp per node ----------------
__device__ __forceinline__ float dot4(float4 a, float4 b) {
    return fmaf(a.x,b.x, fmaf(a.y,b.y, fmaf(a.z,b.z, a.w*b.w)));
}

__global__ void __launch_bounds__(128) k_attn(int s, const float* __restrict__ Wo,
                                              float* __restrict__ y) {
    __shared__ float wo[256];
    __shared__ float aggS[4][25][17];
    int tid = threadIdx.x;
    wo[tid]       = Wo[tid];
    wo[tid + 128] = Wo[tid + 128];
    __syncthreads();

    int w = tid >> 5, lane = tid & 31;
    int node = blockIdx.x*4 + w;
    int h = lane & 3, l0 = lane >> 2;
    int base = h*4;

    const float4* qp = (const float4*)(g_q + (size_t)node*400);
    float4 q0 = qp[lane], q1 = qp[lane+32], q2 = qp[lane+64];
    float4 q3 = (lane < 4) ? qp[lane+96] : make_float4(0,0,0,0);

    float4 a0 = make_float4(0,0,0,0), a1 = a0, a2 = a0, a3 = a0;
    float m = -CUDART_INF_F, ssum = 0.0f;

    int rs = g_row[node], ren = g_row[node+1];
    const float* eb  = g_escal[s][0];
    const float* eg  = g_escal[s][1];
    const float* eg2 = g_escal[s][2];

    for (int p = rs; p < ren; p++) {
        int j = g_col[p];
        const float4* kp = (const float4*)(g_k + (size_t)j*400);
        float4 k0 = kp[lane], k1 = kp[lane+32], k2 = kp[lane+64];
        float part = dot4(q0,k0) + dot4(q1,k1) + dot4(q2,k2);
        if (lane < 4) { float4 k3 = kp[lane+96]; part += dot4(q3,k3); }
        part += __shfl_xor_sync(FULLMASK, part, 4);
        part += __shfl_xor_sync(FULLMASK, part, 8);
        part += __shfl_xor_sync(FULLMASK, part, 16);

        float logit = fmaf(part, 0.1f, eb[p*4+h]);
        float gg  = eg [p*4+h];
        float gg2 = eg2[p*4+h];
        float shv = (lane < 25) ? g_sh[p*25+lane] : 0.0f;

        float nm   = fmaxf(m, logit);
        float corr = expf(m - nm);
        float wgt  = expf(logit - nm);
        ssum = fmaf(ssum, corr, wgt);
        m = nm;

        const float4* vp = (const float4*)(g_v + (size_t)j*400);
        float4 v00 = vp[h];   // v[j][l=0][h][:]
        float4 va = vp[lane], vb = vp[lane+32], vc = vp[lane+64];
        float wg  = wgt*gg;
        float wg2 = wgt*gg2;
        float s0 = __shfl_sync(FULLMASK, shv, l0);
        float s1 = __shfl_sync(FULLMASK, shv, l0+8);
        float s2 = __shfl_sync(FULLMASK, shv, l0+16);
        float s3 = __shfl_sync(FULLMASK, shv, 24);

        float t0;
        t0 = wg*s0;
        a0.x = fmaf(t0,v00.x, fmaf(wg2,va.x, a0.x*corr));
        a0.y = fmaf(t0,v00.y, fmaf(wg2,va.y, a0.y*corr));
        a0.z = fmaf(t0,v00.z, fmaf(wg2,va.z, a0.z*corr));
        a0.w = fmaf(t0,v00.w, fmaf(wg2,va.w, a0.w*corr));
        t0 = wg*s1;
        a1.x = fmaf(t0,v00.x, fmaf(wg2,vb.x, a1.x*corr));
        a1.y = fmaf(t0,v00.y, fmaf(wg2,vb.y, a1.y*corr));
        a1.z = fmaf(t0,v00.z, fmaf(wg2,vb.z, a1.z*corr));
        a1.w = fmaf(t0,v00.w, fmaf(wg2,vb.w, a1.w*corr));
        t0 = wg*s2;
        a2.x = fmaf(t0,v00.x, fmaf(wg2,vc.x, a2.x*corr));
        a2.y = fmaf(t0,v00.y, fmaf(wg2,vc.y, a2.y*corr));
        a2.z = fmaf(t0,v00.z, fmaf(wg2,vc.z, a2.z*corr));
        a2.w = fmaf(t0,v00.w, fmaf(wg2,vc.w, a2.w*corr));
        if (lane < 4) {
            float4 vd = vp[lane+96];
            t0 = wg*s3;
            a3.x = fmaf(t0,v00.x, fmaf(wg2,vd.x, a3.x*corr));
            a3.y = fmaf(t0,v00.y, fmaf(wg2,vd.y, a3.y*corr));
            a3.z = fmaf(t0,v00.z, fmaf(wg2,vd.z, a3.z*corr));
            a3.w = fmaf(t0,v00.w, fmaf(wg2,vd.w, a3.w*corr));
        }
    }

    float invs = 1.0f/(ssum + 1e-9f);
    a0.x*=invs; a0.y*=invs; a0.z*=invs; a0.w*=invs;
    a1.x*=invs; a1.y*=invs; a1.z*=invs; a1.w*=invs;
    a2.x*=invs; a2.y*=invs; a2.z*=invs; a2.w*=invs;
    a3.x*=invs; a3.y*=invs; a3.z*=invs; a3.w*=invs;

    aggS[w][l0   ][base+0]=a0.x; aggS[w][l0   ][base+1]=a0.y; aggS[w][l0   ][base+2]=a0.z; aggS[w][l0   ][base+3]=a0.w;
    aggS[w][l0+8 ][base+0]=a1.x; aggS[w][l0+8 ][base+1]=a1.y; aggS[w][l0+8 ][base+2]=a1.z; aggS[w][l0+8 ][base+3]=a1.w;
    aggS[w][l0+16][base+0]=a2.x; aggS[w][l0+16][base+1]=a2.y; aggS[w][l0+16][base+2]=a2.z; aggS[w][l0+16][base+3]=a2.w;
    if (lane < 4) {
        aggS[w][24][base+0]=a3.x; aggS[w][24][base+1]=a3.y; aggS[w][24][base+2]=a3.z; aggS[w][24][base+3]=a3.w;
    }
    __syncwarp();

    float* yp = y + (size_t)node*400;
    #pragma unroll
    for (int c = 0; c < 4; c++) {
        int l = l0 + 8*c;
        if (c == 3) { if (lane >= 4) break; l = 24; }
        float4 o = make_float4(0,0,0,0);
        #pragma unroll
        for (int f2 = 0; f2 < 16; f2++) {
            float af = aggS[w][l][f2];
            float4 wr = *(const float4*)&wo[f2*16 + base];
            o.x = fmaf(af, wr.x, o.x);
            o.y = fmaf(af, wr.y, o.y);
            o.z = fmaf(af, wr.z, o.z);
            o.w = fmaf(af, wr.w, o.w);
        }
        float4 yv = *(const float4*)&yp[l*16 + base];
        yv.x += o.x; yv.y += o.y; yv.z += o.z; yv.w += o.w;
        *(float4*)&yp[l*16 + base] = yv;
    }
}

// ---------------- final: y[:,0,:] += emb[Z] @ W_embed + b_embed ----------------
__global__ void k_final(const int* __restrict__ Z, const float* __restrict__ emb,
                        const float* __restrict__ We, const float* __restrict__ be,
                        float* __restrict__ y) {
    int gid = blockIdx.x*blockDim.x + threadIdx.x;
    if (gid >= NN*16) return;
    int n = gid >> 4, f = gid & 15;
    int z = Z[n];
    float a = __ldg(&be[f]);
    #pragma unroll
    for (int ff = 0; ff < 16; ff++)
        a = fmaf(__ldg(&emb[z*16+ff]), __ldg(&We[ff*16+f]), a);
    y[(size_t)n*400 + f] += a;
}

// ---------------- launch ----------------
extern "C" void kernel_launch(void* const* d_in, const int* in_sizes, int n_in,
                              void* d_out, int out_size) {
    const int*   Z    = (const int*)d_in[0];
    const int*   ni   = (const int*)d_in[1];
    const float* disp = (const float*)d_in[2];
    const float* emb  = (const float*)d_in[3];
    const float* We   = (const float*)d_in[4];
    const float* be   = (const float*)d_in[5];
    const float* Wrb  = (const float*)d_in[6];
    const float* Wq   = (const float*)d_in[7];
    const float* Wk   = (const float*)d_in[8];
    const float* Wv   = (const float*)d_in[9];
    const float* Wo   = (const float*)d_in[10];
    const float* Wb   = (const float*)d_in[11];
    const float* Wg   = (const float*)d_in[12];
    const float* Wg2  = (const float*)d_in[13];
    float* y = (float*)d_out;

    k_zero   <<<(NN+255)/256, 256>>>();
    k_hist   <<<(EE+255)/256, 256>>>(ni);
    k_scan   <<<1, 1024>>>();
    k_scatter<<<(EE+255)/256, 256>>>(ni);
    k_geom   <<<(EE+255)/256, 256>>>(disp);
    k_edgescal<<<512, 128>>>(Wb, Wg, Wg2);
    k_init   <<<NN/4, 128>>>(emb, Wrb, Z, y);
    for (int s = 0; s < 2; s++) {
        k_proj<<<RPROJ/16, dim3(16,16)>>>(y, Wq + s*256, Wk + s*256, Wv + s*256);
        k_attn<<<NN/4, 128>>>(s, Wo + s*256, y);
    }
    k_final<<<(NN*16+255)/256, 256>>>(Z, emb, We, be, y);
}

// round 2
// speedup vs baseline: 1.0655x; 1.0655x over previous
#include <cuda_runtime.h>
#include <cuda_fp16.h>
#include <math_constants.h>
#include <cstdint>

#define NN 10000
#define EE 160000
#define RPROJ (NN*25)   // 250000 rows
#define FULLMASK 0xffffffffu

// ---------------- scratch (device globals: allocation-free) ----------------
__device__ int   g_count[NN];
__device__ int   g_row[NN+1];
__device__ int   g_head[NN];
__device__ int   g_col[EE];
__device__ int   g_esrc[EE];
__device__ float g_rbf[EE*16];
__device__ float g_sh[EE*25];
__device__ float g_epack[2][EE*12];   // [step][p*12 + {b:0-3, g:4-7, g2:8-11}]
__device__ float g_q[RPROJ*16];
__device__ __align__(16) __half g_kh[RPROJ*16];
__device__ __align__(16) __half g_vh[RPROJ*16];

// ---------------- CSR build ----------------
__global__ void k_zero() {
    int i = blockIdx.x*blockDim.x + threadIdx.x;
    if (i < NN) g_count[i] = 0;
}

__global__ void k_hist(const int2* __restrict__ ni) {
    int e = blockIdx.x*blockDim.x + threadIdx.x;
    if (e < EE) atomicAdd(&g_count[ni[e].x], 1);
}

__global__ void k_scan() {   // one block of 1024 threads, 10 items each
    __shared__ int sums[1024];
    int t = threadIdx.x;
    int base = t*10;
    int loc[10];
    int run = 0;
    #pragma unroll
    for (int i = 0; i < 10; i++) {
        int idx = base + i;
        int c = (idx < NN) ? g_count[idx] : 0;
        loc[i] = run; run += c;
    }
    sums[t] = run;
    __syncthreads();
    for (int off = 1; off < 1024; off <<= 1) {
        int v = 0;
        if (t >= off) v = sums[t-off];
        __syncthreads();
        sums[t] += v;
        __syncthreads();
    }
    int excl = (t == 0) ? 0 : sums[t-1];
    #pragma unroll
    for (int i = 0; i < 10; i++) {
        int idx = base + i;
        if (idx < NN) { int r = excl + loc[i]; g_row[idx] = r; g_head[idx] = r; }
    }
    if (t == 1023) g_row[NN] = sums[1023];
}

__global__ void k_scatter(const int2* __restrict__ ni) {
    int e = blockIdx.x*blockDim.x + threadIdx.x;
    if (e < EE) {
        int2 p2 = ni[e];
        int pos = atomicAdd(&g_head[p2.x], 1);
        g_col[pos]  = p2.y;
        g_esrc[pos] = e;
    }
}

// ---------------- per-edge geometry: rbf (recurrence) + spherical harmonics ----------------
__global__ void k_geom(const float* __restrict__ disp) {
    int p = blockIdx.x*blockDim.x + threadIdx.x;
    if (p >= EE) return;
    int e = g_esrc[p];
    float dx = disp[3*e], dy = disp[3*e+1], dz = disp[3*e+2];
    float d  = sqrtf(dx*dx + dy*dy + dz*dz);
    float ds = fmaxf(d, 1e-9f);
    float inv = 1.0f/ds;
    float x = dx*inv, y = dy*inv, z = dz*inv;

    float env = 0.5f*(cospif(fminf(ds, 5.0f)*0.2f) + 1.0f);
    float t = ds*0.2f;
    float rbf[16];
    if (t < 1e-7f) {
        #pragma unroll
        for (int kk = 0; kk < 16; kk++) rbf[kk] = env;
    } else {
        float s1, c1;
        sincospif(t, &s1, &c1);
        float twoc = 2.0f*c1;
        float invt = env / (CUDART_PI_F * t);
        float skm = 0.0f, sk = s1;
        #pragma unroll
        for (int kk = 0; kk < 16; kk++) {
            rbf[kk] = sk * invt * (1.0f/(float)(kk+1));
            float nx = twoc*sk - skm;
            skm = sk; sk = nx;
        }
    }
    float4* rp = (float4*)(g_rbf + (size_t)p*16);
    rp[0] = make_float4(rbf[0],rbf[1],rbf[2],rbf[3]);
    rp[1] = make_float4(rbf[4],rbf[5],rbf[6],rbf[7]);
    rp[2] = make_float4(rbf[8],rbf[9],rbf[10],rbf[11]);
    rp[3] = make_float4(rbf[12],rbf[13],rbf[14],rbf[15]);

    float x2 = x*x, y2 = y*y, z2 = z*z;
    float sh[25];
    sh[0]  = 0.28209479177387814f;
    sh[1]  = 0.4886025119029199f*y;
    sh[2]  = 0.4886025119029199f*z;
    sh[3]  = 0.4886025119029199f*x;
    sh[4]  = 1.0925484305920792f*x*y;
    sh[5]  = 1.0925484305920792f*y*z;
    sh[6]  = 0.31539156525252005f*(3.0f*z2 - 1.0f);
    sh[7]  = 1.0925484305920792f*x*z;
    sh[8]  = 0.5462742152960396f*(x2 - y2);
    sh[9]  = 0.5900435899266435f*y*(3.0f*x2 - y2);
    sh[10] = 2.890611442640554f*x*y*z;
    sh[11] = 0.4570457994644658f*y*(5.0f*z2 - 1.0f);
    sh[12] = 0.3731763325901154f*z*(5.0f*z2 - 3.0f);
    sh[13] = 0.4570457994644658f*x*(5.0f*z2 - 1.0f);
    sh[14] = 1.445305721320277f*z*(x2 - y2);
    sh[15] = 0.5900435899266435f*x*(x2 - 3.0f*y2);
    sh[16] = 2.5033429417967046f*x*y*(x2 - y2);
    sh[17] = 1.7701307697799304f*y*z*(3.0f*x2 - y2);
    sh[18] = 0.9461746957575601f*x*y*(7.0f*z2 - 1.0f);
    sh[19] = 0.6690465435572892f*y*z*(7.0f*z2 - 3.0f);
    sh[20] = 0.10578554691520431f*(35.0f*z2*z2 - 30.0f*z2 + 3.0f);
    sh[21] = 0.6690465435572892f*x*z*(7.0f*z2 - 3.0f);
    sh[22] = 0.47308734787878004f*(x2 - y2)*(7.0f*z2 - 1.0f);
    sh[23] = 1.7701307697799304f*x*z*(x2 - 3.0f*y2);
    sh[24] = 0.6258357354491761f*(x2*x2 - 6.0f*x2*y2 + y2*y2);
    #pragma unroll
    for (int i = 0; i < 25; i++) g_sh[p*25+i] = sh[i];
}

// ---------------- edge scalars: b0 @ {Wb,Wg,Wg2}[s] for both steps ----------------
// Lane c<24 owns one (type, step, head) output column; weights live in registers.
__global__ void k_edgescal(const float* __restrict__ Wb,
                           const float* __restrict__ Wg,
                           const float* __restrict__ Wg2) {
    int lane = threadIdx.x & 31;
    int warp = (blockIdx.x*blockDim.x + threadIdx.x) >> 5;
    int nwarps = (gridDim.x*blockDim.x) >> 5;
    int c = lane;
    int t = c >> 3, s = (c >> 2) & 1, h = c & 3;
    float wreg[16];
    if (c < 24) {
        const float* W = (t == 0) ? Wb : ((t == 1) ? Wg : Wg2);
        #pragma unroll
        for (int f = 0; f < 16; f++) wreg[f] = __ldg(&W[s*64 + f*4 + h]);
    } else {
        #pragma unroll
        for (int f = 0; f < 16; f++) wreg[f] = 0.0f;
    }
    for (int p = warp; p < EE; p += nwarps) {
        float rv = (lane < 16) ? g_rbf[p*16+lane] : 0.0f;
        float out = 0.0f;
        #pragma unroll
        for (int f = 0; f < 16; f++)
            out = fmaf(__shfl_sync(FULLMASK, rv, f), wreg[f], out);
        if (c < 24) g_epack[s][p*12 + t*4 + h] = out;
    }
}

// ---------------- y init: y[:,0,:] = segsum(rbf*emb[Zj]) @ W_rb, rest 0 ----------------
__global__ void k_init(const float* __restrict__ emb, const float* __restrict__ Wrb,
                       const int* __restrict__ Z, float* __restrict__ y) {
    int tid = threadIdx.x;
    int w = tid >> 5, lane = tid & 31;
    int node = blockIdx.x*4 + w;
    if (node >= NN) return;
    int f = lane & 15, which = lane >> 4;
    int rs = g_row[node], ren = g_row[node+1];
    float acc = 0.0f;
    for (int p = rs + which; p < ren; p += 2) {
        int j = g_col[p];
        int z = Z[j];
        acc = fmaf(g_rbf[p*16+f], __ldg(&emb[z*16+f]), acc);
    }
    acc += __shfl_xor_sync(FULLMASK, acc, 16);
    float out = 0.0f;
    #pragma unroll
    for (int ff = 0; ff < 16; ff++)
        out = fmaf(__shfl_sync(FULLMASK, acc, ff), __ldg(&Wrb[ff*16+f]), out);
    float* yp = y + (size_t)node*400;
    if (lane < 16) yp[f] = out;
    for (int i = 16 + lane; i < 400; i += 32) yp[i] = 0.0f;
}

// ---------------- q,k,v projection: q fp32, k/v fp16 ----------------
__global__ void k_proj(const float* __restrict__ y,
                       const float* __restrict__ Wq,
                       const float* __restrict__ Wk,
                       const float* __restrict__ Wv) {
    __shared__ float yt[16][17];
    __shared__ float wq[16][16], wk[16][16], wv[16][16];
    int tx = threadIdx.x, ty = threadIdx.y;
    int tid = ty*16 + tx;
    wq[ty][tx] = Wq[tid]; wk[ty][tx] = Wk[tid]; wv[ty][tx] = Wv[tid];
    int r = blockIdx.x*16 + ty;
    yt[ty][tx] = (r < RPROJ) ? y[(size_t)r*16 + tx] : 0.0f;
    __syncthreads();
    if (r >= RPROJ) return;
    float aq = 0.0f, ak = 0.0f, av = 0.0f;
    #pragma unroll
    for (int f = 0; f < 16; f++) {
        float yv = yt[ty][f];
        aq = fmaf(yv, wq[f][tx], aq);
        ak = fmaf(yv, wk[f][tx], ak);
        av = fmaf(yv, wv[f][tx], av);
    }
    g_q [(size_t)r*16+tx] = aq;
    g_kh[(size_t)r*16+tx] = __float2half_rn(ak);
    g_vh[(size_t)r*16+tx] = __float2half_rn(av);
}

// ---------------- attention + aggregate + Wo, one warp per node ----------------
__device__ __forceinline__ float dot4(float4 a, float4 b) {
    return fmaf(a.x,b.x, fmaf(a.y,b.y, fmaf(a.z,b.z, a.w*b.w)));
}
__device__ __forceinline__ float4 h2f4(uint2 u) {
    __half2 a = *(__half2*)&u.x;
    __half2 b = *(__half2*)&u.y;
    float2 fa = __half22float2(a), fb = __half22float2(b);
    return make_float4(fa.x, fa.y, fb.x, fb.y);
}

__global__ void __launch_bounds__(128) k_attn(int s, const float* __restrict__ Wo,
                                              float* __restrict__ y) {
    __shared__ float wo[256];
    __shared__ float aggS[4][25][17];
    int tid = threadIdx.x;
    wo[tid]       = Wo[tid];
    wo[tid + 128] = Wo[tid + 128];
    __syncthreads();

    int w = tid >> 5, lane = tid & 31;
    int node = blockIdx.x*4 + w;
    int h = lane & 3, l0 = lane >> 2;
    int base = h*4;

    const float4* qp = (const float4*)(g_q + (size_t)node*400);
    float4 q0 = qp[lane], q1 = qp[lane+32], q2 = qp[lane+64];
    float4 q3 = (lane < 4) ? qp[lane+96] : make_float4(0,0,0,0);

    float4 a0 = make_float4(0,0,0,0), a1 = a0, a2 = a0, a3 = a0;
    float m = -CUDART_INF_F, ssum = 0.0f;

    int rs = g_row[node], ren = g_row[node+1];
    const float* ep = g_epack[s];

    for (int p = rs; p < ren; p++) {
        int j = g_col[p];
        const uint2* kp = (const uint2*)(g_kh + (size_t)j*400);
        float4 k0 = h2f4(kp[lane]);
        float4 k1 = h2f4(kp[lane+32]);
        float4 k2 = h2f4(kp[lane+64]);
        float part = dot4(q0,k0) + dot4(q1,k1) + dot4(q2,k2);
        if (lane < 4) { float4 k3 = h2f4(kp[lane+96]); part += dot4(q3,k3); }
        part += __shfl_xor_sync(FULLMASK, part, 4);
        part += __shfl_xor_sync(FULLMASK, part, 8);
        part += __shfl_xor_sync(FULLMASK, part, 16);

        float logit = fmaf(part, 0.1f, ep[p*12+h]);
        float gg  = ep[p*12+4+h];
        float gg2 = ep[p*12+8+h];
        float shv = (lane < 25) ? g_sh[p*25+lane] : 0.0f;

        float nm   = fmaxf(m, logit);
        float corr = __expf(m - nm);
        float wgt  = __expf(logit - nm);
        ssum = fmaf(ssum, corr, wgt);
        m = nm;

        const uint2* vp = (const uint2*)(g_vh + (size_t)j*400);
        float4 v00 = h2f4(vp[h]);   // v[j][l=0][h][:]
        float4 va = h2f4(vp[lane]);
        float4 vb = h2f4(vp[lane+32]);
        float4 vc = h2f4(vp[lane+64]);
        float wg  = wgt*gg;
        float wg2 = wgt*gg2;
        float s0 = __shfl_sync(FULLMASK, shv, l0);
        float s1 = __shfl_sync(FULLMASK, shv, l0+8);
        float s2 = __shfl_sync(FULLMASK, shv, l0+16);
        float s3 = __shfl_sync(FULLMASK, shv, 24);

        float t0;
        t0 = wg*s0;
        a0.x = fmaf(t0,v00.x, fmaf(wg2,va.x, a0.x*corr));
        a0.y = fmaf(t0,v00.y, fmaf(wg2,va.y, a0.y*corr));
        a0.z = fmaf(t0,v00.z, fmaf(wg2,va.z, a0.z*corr));
        a0.w = fmaf(t0,v00.w, fmaf(wg2,va.w, a0.w*corr));
        t0 = wg*s1;
        a1.x = fmaf(t0,v00.x, fmaf(wg2,vb.x, a1.x*corr));
        a1.y = fmaf(t0,v00.y, fmaf(wg2,vb.y, a1.y*corr));
        a1.z = fmaf(t0,v00.z, fmaf(wg2,vb.z, a1.z*corr));
        a1.w = fmaf(t0,v00.w, fmaf(wg2,vb.w, a1.w*corr));
        t0 = wg*s2;
        a2.x = fmaf(t0,v00.x, fmaf(wg2,vc.x, a2.x*corr));
        a2.y = fmaf(t0,v00.y, fmaf(wg2,vc.y, a2.y*corr));
        a2.z = fmaf(t0,v00.z, fmaf(wg2,vc.z, a2.z*corr));
        a2.w = fmaf(t0,v00.w, fmaf(wg2,vc.w, a2.w*corr));
        if (lane < 4) {
            float4 vd = h2f4(vp[lane+96]);
            t0 = wg*s3;
            a3.x = fmaf(t0,v00.x, fmaf(wg2,vd.x, a3.x*corr));
            a3.y = fmaf(t0,v00.y, fmaf(wg2,vd.y, a3.y*corr));
            a3.z = fmaf(t0,v00.z, fmaf(wg2,vd.z, a3.z*corr));
            a3.w = fmaf(t0,v00.w, fmaf(wg2,vd.w, a3.w*corr));
        }
    }

    float invs = 1.0f/(ssum + 1e-9f);
    a0.x*=invs; a0.y*=invs; a0.z*=invs; a0.w*=invs;
    a1.x*=invs; a1.y*=invs; a1.z*=invs; a1.w*=invs;
    a2.x*=invs; a2.y*=invs; a2.z*=invs; a2.w*=invs;
    a3.x*=invs; a3.y*=invs; a3.z*=invs; a3.w*=invs;

    aggS[w][l0   ][base+0]=a0.x; aggS[w][l0   ][base+1]=a0.y; aggS[w][l0   ][base+2]=a0.z; aggS[w][l0   ][base+3]=a0.w;
    aggS[w][l0+8 ][base+0]=a1.x; aggS[w][l0+8 ][base+1]=a1.y; aggS[w][l0+8 ][base+2]=a1.z; aggS[w][l0+8 ][base+3]=a1.w;
    aggS[w][l0+16][base+0]=a2.x; aggS[w][l0+16][base+1]=a2.y; aggS[w][l0+16][base+2]=a2.z; aggS[w][l0+16][base+3]=a2.w;
    if (lane < 4) {
        aggS[w][24][base+0]=a3.x; aggS[w][24][base+1]=a3.y; aggS[w][24][base+2]=a3.z; aggS[w][24][base+3]=a3.w;
    }
    __syncwarp();

    float* yp = y + (size_t)node*400;
    #pragma unroll
    for (int c = 0; c < 4; c++) {
        int l = l0 + 8*c;
        if (c == 3) { if (lane >= 4) break; l = 24; }
        float4 o = make_float4(0,0,0,0);
        #pragma unroll
        for (int f2 = 0; f2 < 16; f2++) {
            float af = aggS[w][l][f2];
            float4 wr = *(const float4*)&wo[f2*16 + base];
            o.x = fmaf(af, wr.x, o.x);
            o.y = fmaf(af, wr.y, o.y);
            o.z = fmaf(af, wr.z, o.z);
            o.w = fmaf(af, wr.w, o.w);
        }
        float4 yv = *(const float4*)&yp[l*16 + base];
        yv.x += o.x; yv.y += o.y; yv.z += o.z; yv.w += o.w;
        *(float4*)&yp[l*16 + base] = yv;
    }
}

// ---------------- final: y[:,0,:] += emb[Z] @ W_embed + b_embed ----------------
__global__ void k_final(const int* __restrict__ Z, const float* __restrict__ emb,
                        const float* __restrict__ We, const float* __restrict__ be,
                        float* __restrict__ y) {
    int gid = blockIdx.x*blockDim.x + threadIdx.x;
    if (gid >= NN*16) return;
    int n = gid >> 4, f = gid & 15;
    int z = Z[n];
    float a = __ldg(&be[f]);
    #pragma unroll
    for (int ff = 0; ff < 16; ff++)
        a = fmaf(__ldg(&emb[z*16+ff]), __ldg(&We[ff*16+f]), a);
    y[(size_t)n*400 + f] += a;
}

// ---------------- launch ----------------
extern "C" void kernel_launch(void* const* d_in, const int* in_sizes, int n_in,
                              void* d_out, int out_size) {
    const int*   Z    = (const int*)d_in[0];
    const int2*  ni   = (const int2*)d_in[1];
    const float* disp = (const float*)d_in[2];
    const float* emb  = (const float*)d_in[3];
    const float* We   = (const float*)d_in[4];
    const float* be   = (const float*)d_in[5];
    const float* Wrb  = (const float*)d_in[6];
    const float* Wq   = (const float*)d_in[7];
    const float* Wk   = (const float*)d_in[8];
    const float* Wv   = (const float*)d_in[9];
    const float* Wo   = (const float*)d_in[10];
    const float* Wb   = (const float*)d_in[11];
    const float* Wg   = (const float*)d_in[12];
    const float* Wg2  = (const float*)d_in[13];
    float* y = (float*)d_out;

    k_zero   <<<(NN+255)/256, 256>>>();
    k_hist   <<<(EE+255)/256, 256>>>(ni);
    k_scan   <<<1, 1024>>>();
    k_scatter<<<(EE+255)/256, 256>>>(ni);
    k_geom   <<<(EE+255)/256, 256>>>(disp);
    k_edgescal<<<512, 128>>>(Wb, Wg, Wg2);
    k_init   <<<NN/4, 128>>>(emb, Wrb, Z, y);
    for (int s = 0; s < 2; s++) {
        k_proj<<<RPROJ/16, dim3(16,16)>>>(y, Wq + s*256, Wk + s*256, Wv + s*256);
        k_attn<<<NN/4, 128>>>(s, Wo + s*256, y);
    }
    k_final<<<(NN*16+255)/256, 256>>>(Z, emb, We, be, y);
}